// round 15
// baseline (speedup 1.0000x reference)
#include <cuda_runtime.h>
#include <cuda_fp16.h>
#include <cstdint>

// ---------------- problem constants ----------------
#define BATCH   65536
#define IN_F    1024
#define OUT_F   1024
#define BM      128
#define BN      128
#define BK      64
#define NK      (IN_F / BK)      // 16 k-chunks
#define NTHREADS 256
#define STAGES  5

#define STAGE_BYTES 16384        // A only: 128x64 fp16 (128B rows)
#define SMEM_PAD    2048
#define SMEM_TOTAL  (SMEM_PAD + STAGES * STAGE_BYTES)   // 83968 -> 2 CTAs/SM

// smem offsets for mbarriers
#define MB_FULL   0              // 5 x 8B
#define MB_EMPTY  40             // 5 x 8B

// fp16 copies (round-nearest).
__device__ __half g_Xh[(size_t)BATCH * IN_F];   // 128 MB scratch
__device__ __half g_Wh[(size_t)OUT_F * IN_F];   // 2 MB scratch (L2/L1 resident)

// ---------------- helpers ----------------
__device__ __forceinline__ uint32_t h2_u32(__half2 h) {
    union { __half2 h; uint32_t u; } c; c.h = h; return c.u;
}
__device__ __forceinline__ uint32_t smem_u32(const void* p) {
    uint32_t a;
    asm("{ .reg .u64 t; cvta.to.shared.u64 t, %1; cvt.u32.u64 %0, t; }" : "=r"(a) : "l"(p));
    return a;
}
__device__ __forceinline__ void cp16(uint32_t s, const void* g) {
    asm volatile("cp.async.cg.shared.global [%0], [%1], 16;" :: "r"(s), "l"(g));
}
__device__ __forceinline__ uint32_t ldg_u32(const __half* p) {
    return __ldg((const uint32_t*)p);
}

#define MBAR_INIT(addr, cnt) \
    asm volatile("mbarrier.init.shared.b64 [%0], %1;" :: "r"(addr), "r"(cnt) : "memory")
#define MBAR_ARRIVE(addr) \
    asm volatile("mbarrier.arrive.shared.b64 _, [%0];" :: "r"(addr) : "memory")
#define CP_ARRIVE_NOINC(addr) \
    asm volatile("cp.async.mbarrier.arrive.noinc.shared::cta.b64 [%0];" :: "r"(addr) : "memory")

#define MBAR_WAIT_PARITY(addr, par) do {                                          \
    uint32_t _m = (addr); uint32_t _p = (par); uint32_t _d;                       \
    asm volatile("{\n\t.reg .pred p;\n\t"                                         \
        "mbarrier.try_wait.parity.acquire.cta.shared::cta.b64 p, [%1], %2;\n\t"   \
        "selp.b32 %0, 1, 0, p;\n\t}"                                              \
        : "=r"(_d) : "r"(_m), "r"(_p) : "memory");                                \
    if (!_d) {                                                                    \
        asm volatile("{\n\t.reg .pred P1;\n\t"                                    \
            "WL_%=:\n\t"                                                          \
            "mbarrier.try_wait.parity.acquire.cta.shared::cta.b64 P1, [%0], %1, 0x989680;\n\t" \
            "@P1 bra.uni WD_%=;\n\t"                                              \
            "bra.uni WL_%=;\n\t"                                                  \
            "WD_%=:\n\t}" :: "r"(_m), "r"(_p) : "memory");                        \
    } } while (0)

#define LDSM4(R, A) \
    asm volatile("ldmatrix.sync.aligned.m8n8.x4.shared.b16 {%0,%1,%2,%3}, [%4];" \
        : "=r"((R)[0]), "=r"((R)[1]), "=r"((R)[2]), "=r"((R)[3]) : "r"(A))

#define MMA_F16(D, A, B0, B1) \
    asm volatile("mma.sync.aligned.m16n8k16.row.col.f32.f16.f16.f32 " \
        "{%0,%1,%2,%3}, {%4,%5,%6,%7}, {%8,%9}, {%0,%1,%2,%3};" \
        : "+f"((D)[0]), "+f"((D)[1]), "+f"((D)[2]), "+f"((D)[3]) \
        : "r"((A)[0]), "r"((A)[1]), "r"((A)[2]), "r"((A)[3]), "r"(B0), "r"(B1))

__device__ __forceinline__ float tanh_ap(float x) {
    float y; asm("tanh.approx.f32 %0, %1;" : "=f"(y) : "f"(x)); return y;
}
__device__ __forceinline__ float sin_ap(float x) {
    float y; asm("sin.approx.f32 %0, %1;" : "=f"(y) : "f"(x)); return y;
}

// ---------------- conversion: X then W in one launch (fp32 -> fp16 RN) ----------
#define XVECS ((size_t)BATCH * IN_F / 8)
__global__ void __launch_bounds__(256)
cvt_xw_kernel(const float4* __restrict__ Xin, const float4* __restrict__ Win) {
    size_t i = (size_t)blockIdx.x * 256 + threadIdx.x;
    const float4* src;
    uint4* dst;
    if (i < XVECS) { src = Xin + 2 * i; dst = (uint4*)g_Xh + i; }
    else           { size_t j = i - XVECS; src = Win + 2 * j; dst = (uint4*)g_Wh + j; }
    float4 v0 = src[0], v1 = src[1];
    uint4 o = { h2_u32(__floats2half2_rn(v0.x, v0.y)),
                h2_u32(__floats2half2_rn(v0.z, v0.w)),
                h2_u32(__floats2half2_rn(v1.x, v1.y)),
                h2_u32(__floats2half2_rn(v1.z, v1.w)) };
    *dst = o;
}

// ---------------- fused fp16 GEMM: A smem-staged, B register-direct from L1/L2 ----
__global__ void __launch_bounds__(NTHREADS, 2)
gemm_act_kernel(const float* __restrict__ Bv, float* __restrict__ O) {
    extern __shared__ char smem[];
    const uint32_t sb = smem_u32(smem);
    const uint32_t tiles = ((sb + 127) & ~127u) + SMEM_PAD - 128;

    const int tid = threadIdx.x;
    const int wid = tid >> 5;
    const int lane = tid & 31;
    const int warp_m = wid & 3;       // 0..3 -> m offset *32
    const int warp_n = wid >> 2;      // 0..1 -> n offset *64

    const int nt = blockIdx.x & 7;    // 8 N-tiles; consecutive bids share A tile in L2
    const int mt = blockIdx.x >> 3;   // 512 M-tiles
    const int m0 = mt * BM;
    const int n0 = nt * BN;

    // ---- mbarrier init ----
    if (tid == 0) {
        #pragma unroll
        for (int s = 0; s < STAGES; ++s) {
            MBAR_INIT(sb + MB_FULL  + s * 8, NTHREADS);   // cp.async completions
            MBAR_INIT(sb + MB_EMPTY + s * 8, 8);          // one arrive per warp
        }
    }
    __syncthreads();

    // ---- producer addressing (A only): 1024 vec16/stage, 4 per thread ----
    const int rr = tid >> 3;                  // 0..31
    const int cc = tid & 7;                   // 16B vec
    const uint32_t offA0 = (uint32_t)(rr * 128 + ((cc * 16) ^ ((rr & 7) << 4)));
    const __half* gAt = g_Xh + (size_t)(m0 + rr) * IN_F + cc * 8;

    // ---- A ldmatrix per-thread offset ----
    const int arow = warp_m * 32 + (lane & 15);
    const uint32_t offA = (uint32_t)(arow * 128 + (((lane >> 4) * 16) ^ ((arow & 7) << 4)));

    // ---- B register-direct base pointer ----
    // lane l: g = l>>2 (n within 8-group), t = l&3 (k pair); b0 = W[n][k=2t,2t+1]
    const __half* gW = g_Wh + (size_t)(n0 + warp_n * 64 + (lane >> 2)) * IN_F
                            + 2 * (lane & 3);

    float acc[2][8][4];
    #pragma unroll
    for (int a = 0; a < 2; ++a)
        #pragma unroll
        for (int f = 0; f < 8; ++f)
            #pragma unroll
            for (int c = 0; c < 4; ++c) acc[a][f][c] = 0.0f;

    // ---- prologue: produce all 5 stages (chunks 0..4) ----
    #pragma unroll
    for (int s = 0; s < STAGES; ++s) {
        const uint32_t base = tiles + s * STAGE_BYTES + offA0;
        const __half* a = gAt + s * BK;
        #pragma unroll
        for (int i = 0; i < 4; ++i)
            cp16(base + i * 4096, a + (size_t)i * 32 * IN_F);
        CP_ARRIVE_NOINC(sb + MB_FULL + s * 8);
    }

    // ---- mainloop: mbarrier flow control ----
    uint32_t stg_cons = tiles;
    const uint32_t stg_top = tiles + (STAGES - 1) * STAGE_BYTES;
    int sidx = 0;
    int phase = 0;
    for (int kc = 0; kc < NK; ++kc) {
        MBAR_WAIT_PARITY(sb + MB_FULL + sidx * 8, phase);

        const uint32_t aB = stg_cons + offA;
        const __half* gWk = gW + kc * BK;
        #pragma unroll
        for (int j = 0; j < 4; ++j) {         // 4 x k16 steps per BK=64
            const uint32_t jx = (uint32_t)(j << 5);
            uint32_t a0[4], a1[4];
            LDSM4(a0, aB ^ jx);                     // m 0-15
            LDSM4(a1, (aB + 2048) ^ jx);            // m 16-31
            const __half* wj = gWk + j * 16;
            #pragma unroll
            for (int q = 0; q < 4; ++q) {           // n 16-blocks
                const __half* wq = wj + (size_t)(q * 16) * IN_F;
                uint32_t b0 = ldg_u32(wq);
                uint32_t b1 = ldg_u32(wq + 8);
                uint32_t b2 = ldg_u32(wq + 8 * IN_F);
                uint32_t b3 = ldg_u32(wq + 8 * IN_F + 8);
                MMA_F16(acc[0][2 * q],     a0, b0, b1);
                MMA_F16(acc[1][2 * q],     a1, b0, b1);
                MMA_F16(acc[0][2 * q + 1], a0, b2, b3);
                MMA_F16(acc[1][2 * q + 1], a1, b2, b3);
            }
        }
        // per-warp consumption arrive
        __syncwarp();
        if (lane == 0) MBAR_ARRIVE(sb + MB_EMPTY + sidx * 8);

        // refill just-consumed stage with chunk kc+5
        if (kc + STAGES < NK) {
            MBAR_WAIT_PARITY(sb + MB_EMPTY + sidx * 8, phase);
            const uint32_t base = stg_cons + offA0;
            const __half* a = gAt + (kc + STAGES) * BK;
            #pragma unroll
            for (int i = 0; i < 4; ++i)
                cp16(base + i * 4096, a + (size_t)i * 32 * IN_F);
            CP_ARRIVE_NOINC(sb + MB_FULL + sidx * 8);
        }

        if (stg_cons == stg_top) { stg_cons = tiles; sidx = 0; phase ^= 1; }
        else                     { stg_cons += STAGE_BYTES; ++sidx; }
    }

    // ---- epilogue: bias + cyclic activations, staged through smem ----
    __syncthreads();    // all compute done; reuse smem as output staging

    float bs0[8], bs1[8];
    #pragma unroll
    for (int f = 0; f < 8; ++f) {
        const int cb = n0 + warp_n * 64 + f * 8 + 2 * (lane & 3);
        bs0[f] = __ldg(Bv + cb);
        bs1[f] = __ldg(Bv + cb + 1);
    }

    float* eb = (float*)(smem + (tiles - sb));    // stride-136 staging, 128 rows
    const bool even = (lane & 1) == 0;

    #pragma unroll
    for (int mf = 0; mf < 2; ++mf) {
        #pragma unroll
        for (int h = 0; h < 2; ++h) {
            const int row = warp_m * 32 + mf * 16 + (lane >> 2) + h * 8;
            #pragma unroll
            for (int f = 0; f < 8; ++f) {
                float v0 = acc[mf][f][2 * h]     + bs0[f];
                float v1 = acc[mf][f][2 * h + 1] + bs1[f];
                float o0 = even ? tanh_ap(v0) : fmaxf(v0, 0.0f);            // col%4 0|2
                float o1 = even ? sin_ap(v1)
                                : fmaf(0.5f, tanh_ap(0.5f * v1), 0.5f);     // col%4 1|3
                float2 o = { o0, o1 };
                *(float2*)&eb[(size_t)row * 136 + warp_n * 64 + f * 8 + 2 * (lane & 3)] = o;
            }
        }
    }
    __syncthreads();

    // coalesced 128B streaming stores: 128 rows x 32 float4
    #pragma unroll
    for (int i = 0; i < 16; ++i) {
        const int idx = tid + i * NTHREADS;
        const int row = idx >> 5;
        const int c4  = idx & 31;
        float4 v = *(const float4*)&eb[(size_t)row * 136 + c4 * 4];
        *(float4*)(O + (size_t)(m0 + row) * OUT_F + n0 + c4 * 4) = v;
    }
}

// ---------------- launch ----------------
extern "C" void kernel_launch(void* const* d_in, const int* in_sizes, int n_in,
                              void* d_out, int out_size) {
    const float* X  = (const float*)d_in[0];
    const float* Wt = (const float*)d_in[1];
    const float* Bv = (const float*)d_in[2];
    float* O = (float*)d_out;

    const size_t total_vecs = XVECS + (size_t)OUT_F * IN_F / 8;
    cvt_xw_kernel<<<(int)(total_vecs / 256), 256>>>((const float4*)X, (const float4*)Wt);

    cudaFuncSetAttribute(gemm_act_kernel,
                         cudaFuncAttributeMaxDynamicSharedMemorySize, SMEM_TOTAL);
    gemm_act_kernel<<<(BATCH / BM) * (OUT_F / BN), NTHREADS, SMEM_TOTAL>>>(Bv, O);
}

// round 16
// speedup vs baseline: 3.0226x; 3.0226x over previous
#include <cuda_runtime.h>
#include <cuda_fp16.h>
#include <cstdint>

// ---------------- problem constants ----------------
#define BATCH   65536
#define IN_F    1024
#define OUT_F   1024
#define BM      128
#define BN      128
#define BK      64
#define NK      (IN_F / BK)      // 16 k-chunks
#define NTHREADS 256
#define STAGES  3

#define STAGE_BYTES 32768        // A 16KB (128x64 f16) + B 16KB (128x64 f16)
#define B_OFF       16384
#define SMEM_PAD    2048
#define SMEM_TOTAL  (SMEM_PAD + STAGES * STAGE_BYTES)   // 100352 -> 2 CTAs/SM

// smem offsets (from dynamic smem base) for mbarriers
#define MB_FULL   0              // 3 x 8B
#define MB_EMPTY  24             // 3 x 8B

// fp16 copies (round-nearest). Same 10 mantissa bits as tf32; fp32 accumulate.
__device__ __half g_Xh[(size_t)BATCH * IN_F];   // 128 MB scratch
__device__ __half g_Wh[(size_t)OUT_F * IN_F];   // 2 MB scratch

// ---------------- helpers ----------------
__device__ __forceinline__ uint32_t h2_u32(__half2 h) {
    union { __half2 h; uint32_t u; } c; c.h = h; return c.u;
}
__device__ __forceinline__ uint32_t smem_u32(const void* p) {
    uint32_t a;
    asm("{ .reg .u64 t; cvta.to.shared.u64 t, %1; cvt.u32.u64 %0, t; }" : "=r"(a) : "l"(p));
    return a;
}
__device__ __forceinline__ void cp16(uint32_t s, const void* g) {
    asm volatile("cp.async.cg.shared.global [%0], [%1], 16;" :: "r"(s), "l"(g));
}

#define MBAR_INIT(addr, cnt) \
    asm volatile("mbarrier.init.shared.b64 [%0], %1;" :: "r"(addr), "r"(cnt) : "memory")
#define MBAR_ARRIVE(addr) \
    asm volatile("mbarrier.arrive.shared.b64 _, [%0];" :: "r"(addr) : "memory")
#define CP_ARRIVE_NOINC(addr) \
    asm volatile("cp.async.mbarrier.arrive.noinc.shared::cta.b64 [%0];" :: "r"(addr) : "memory")

#define MBAR_WAIT_PARITY(addr, par) do {                                          \
    uint32_t _m = (addr); uint32_t _p = (par); uint32_t _d;                       \
    asm volatile("{\n\t.reg .pred p;\n\t"                                         \
        "mbarrier.try_wait.parity.acquire.cta.shared::cta.b64 p, [%1], %2;\n\t"   \
        "selp.b32 %0, 1, 0, p;\n\t}"                                              \
        : "=r"(_d) : "r"(_m), "r"(_p) : "memory");                                \
    if (!_d) {                                                                    \
        asm volatile("{\n\t.reg .pred P1;\n\t"                                    \
            "WL_%=:\n\t"                                                          \
            "mbarrier.try_wait.parity.acquire.cta.shared::cta.b64 P1, [%0], %1, 0x989680;\n\t" \
            "@P1 bra.uni WD_%=;\n\t"                                              \
            "bra.uni WL_%=;\n\t"                                                  \
            "WD_%=:\n\t}" :: "r"(_m), "r"(_p) : "memory");                        \
    } } while (0)

#define LDSM4(R, A) \
    asm volatile("ldmatrix.sync.aligned.m8n8.x4.shared.b16 {%0,%1,%2,%3}, [%4];" \
        : "=r"((R)[0]), "=r"((R)[1]), "=r"((R)[2]), "=r"((R)[3]) : "r"(A))

#define MMA_F16(D, A, B0, B1) \
    asm volatile("mma.sync.aligned.m16n8k16.row.col.f32.f16.f16.f32 " \
        "{%0,%1,%2,%3}, {%4,%5,%6,%7}, {%8,%9}, {%0,%1,%2,%3};" \
        : "+f"((D)[0]), "+f"((D)[1]), "+f"((D)[2]), "+f"((D)[3]) \
        : "r"((A)[0]), "r"((A)[1]), "r"((A)[2]), "r"((A)[3]), "r"(B0), "r"(B1))

__device__ __forceinline__ float tanh_ap(float x) {
    float y; asm("tanh.approx.f32 %0, %1;" : "=f"(y) : "f"(x)); return y;
}
__device__ __forceinline__ float sin_ap(float x) {
    float y; asm("sin.approx.f32 %0, %1;" : "=f"(y) : "f"(x)); return y;
}

// ---------------- conversion: X then W in one launch (fp32 -> fp16 RN) ----------
#define XVECS ((size_t)BATCH * IN_F / 8)
__global__ void __launch_bounds__(256)
cvt_xw_kernel(const float4* __restrict__ Xin, const float4* __restrict__ Win) {
    size_t i = (size_t)blockIdx.x * 256 + threadIdx.x;
    const float4* src;
    uint4* dst;
    if (i < XVECS) { src = Xin + 2 * i; dst = (uint4*)g_Xh + i; }
    else           { size_t j = i - XVECS; src = Win + 2 * j; dst = (uint4*)g_Wh + j; }
    float4 v0 = src[0], v1 = src[1];
    uint4 o = { h2_u32(__floats2half2_rn(v0.x, v0.y)),
                h2_u32(__floats2half2_rn(v0.z, v0.w)),
                h2_u32(__floats2half2_rn(v1.x, v1.y)),
                h2_u32(__floats2half2_rn(v1.z, v1.w)) };
    *dst = o;
}

// ---------------- fused fp16 GEMM (fp32 accum) + cyclic activations ----------------
__global__ void __launch_bounds__(NTHREADS, 2)
gemm_act_kernel(const float* __restrict__ Bv, float* __restrict__ O) {
    extern __shared__ char smem[];
    const uint32_t sb = smem_u32(smem);
    const uint32_t tiles = ((sb + 127) & ~127u) + SMEM_PAD - 128;

    const int tid = threadIdx.x;
    const int wid = tid >> 5;
    const int lane = tid & 31;
    const int warp_m = wid & 3;       // 0..3 -> m offset *32
    const int warp_n = wid >> 2;      // 0..1 -> n offset *64

    const int nt = blockIdx.x & 7;    // 8 N-tiles; consecutive bids share A tile in L2
    const int mt = blockIdx.x >> 3;   // 512 M-tiles
    const int m0 = mt * BM;
    const int n0 = nt * BN;

    // ---- mbarrier init ----
    if (tid == 0) {
        #pragma unroll
        for (int s = 0; s < STAGES; ++s) {
            MBAR_INIT(sb + MB_FULL  + s * 8, NTHREADS);   // cp.async completions
            MBAR_INIT(sb + MB_EMPTY + s * 8, 8);          // one arrive per warp
        }
    }
    __syncthreads();

    // ---- producer addressing: row = 128B of fp16 (64 halves) ----
    const int rr = tid >> 3;                  // 0..31
    const int cc = tid & 7;                   // 16B vec
    const uint32_t sw_base = (uint32_t)((cc * 16) ^ ((rr & 7) << 4));
    const __half* gAt = g_Xh + (size_t)(m0 + rr) * IN_F + cc * 8;
    const __half* gBt = g_Wh + (size_t)(n0 + rr) * IN_F + cc * 8;

    // ---- ldmatrix per-thread offsets ----
    const int arow = warp_m * 32 + (lane & 15);
    const uint32_t offA = (uint32_t)(arow * 128 + (((lane >> 4) * 16) ^ ((arow & 7) << 4)));
    const int brow = warp_n * 64 + (lane & 7) + ((lane >> 4) << 3);
    const uint32_t offB = (uint32_t)(brow * 128 + ((((lane >> 3) & 1) * 16) ^ ((brow & 7) << 4)))
                        + B_OFF;

    float acc[2][8][4];
    #pragma unroll
    for (int a = 0; a < 2; ++a)
        #pragma unroll
        for (int f = 0; f < 8; ++f)
            #pragma unroll
            for (int c = 0; c < 4; ++c) acc[a][f][c] = 0.0f;

    // ---- prologue: produce stages 0..2 ----
    #pragma unroll
    for (int s = 0; s < STAGES; ++s) {
        const uint32_t base = tiles + s * STAGE_BYTES + rr * 128 + sw_base;
        const __half* a = gAt + s * BK;
        const __half* b = gBt + s * BK;
        #pragma unroll
        for (int i = 0; i < 4; ++i) {         // A,B: 4 x 32 rows each
            cp16(base + i * 4096,         a + (size_t)i * 32 * IN_F);
            cp16(base + B_OFF + i * 4096, b + (size_t)i * 32 * IN_F);
        }
        CP_ARRIVE_NOINC(sb + MB_FULL + s * 8);
    }

    // ---- mainloop: mbarrier flow control, no CTA-wide barriers ----
    uint32_t stg_cons = tiles;
    const uint32_t stg_top = tiles + (STAGES - 1) * STAGE_BYTES;
    int sidx = 0;          // kc % 3
    int phase = 0;         // (kc / 3) & 1
    for (int kc = 0; kc < NK; ++kc) {
        MBAR_WAIT_PARITY(sb + MB_FULL + sidx * 8, phase);

        const uint32_t aB = stg_cons + offA;
        const uint32_t bB = stg_cons + offB;
        #pragma unroll
        for (int j = 0; j < 4; ++j) {         // 4 x k16 steps per BK=64
            const uint32_t jx = (uint32_t)(j << 5);
            const uint32_t ax = aB ^ jx;
            const uint32_t bx = bB ^ jx;
            uint32_t a0[4], a1[4];
            LDSM4(a0, ax);                          // m 0-15
            LDSM4(a1, ax + 2048);                   // m 16-31
            #pragma unroll
            for (int q = 0; q < 4; ++q) {           // n 16-blocks, 4 live B regs
                uint32_t b[4];
                LDSM4(b, bx + q * 2048);
                MMA_F16(acc[0][2 * q],     a0, b[0], b[1]);
                MMA_F16(acc[1][2 * q],     a1, b[0], b[1]);
                MMA_F16(acc[0][2 * q + 1], a0, b[2], b[3]);
                MMA_F16(acc[1][2 * q + 1], a1, b[2], b[3]);
            }
        }
        // per-warp consumption arrive (MMA is warp-synchronous; syncwarp is cheap)
        __syncwarp();
        if (lane == 0) MBAR_ARRIVE(sb + MB_EMPTY + sidx * 8);

        // refill the just-consumed stage with chunk kc+3
        if (kc + STAGES < NK) {
            MBAR_WAIT_PARITY(sb + MB_EMPTY + sidx * 8, phase);  // all warps consumed
            const uint32_t base = stg_cons + rr * 128 + sw_base;
            const __half* a = gAt + (kc + STAGES) * BK;
            const __half* b = gBt + (kc + STAGES) * BK;
            #pragma unroll
            for (int i = 0; i < 4; ++i) {
                cp16(base + i * 4096,         a + (size_t)i * 32 * IN_F);
                cp16(base + B_OFF + i * 4096, b + (size_t)i * 32 * IN_F);
            }
            CP_ARRIVE_NOINC(sb + MB_FULL + sidx * 8);
        }

        if (stg_cons == stg_top) { stg_cons = tiles; sidx = 0; phase ^= 1; }
        else                     { stg_cons += STAGE_BYTES; ++sidx; }
    }

    // ---- epilogue: bias + cyclic activations, direct gmem float2 stores ----
    float bs0[8], bs1[8];
    #pragma unroll
    for (int f = 0; f < 8; ++f) {
        const int cb = n0 + warp_n * 64 + f * 8 + 2 * (lane & 3);
        bs0[f] = __ldg(Bv + cb);
        bs1[f] = __ldg(Bv + cb + 1);
    }

    const bool even = (lane & 1) == 0;
    float* obase = O + (size_t)m0 * OUT_F + n0 + warp_n * 64 + 2 * (lane & 3);

    #pragma unroll
    for (int mf = 0; mf < 2; ++mf) {
        #pragma unroll
        for (int h = 0; h < 2; ++h) {
            const int row = warp_m * 32 + mf * 16 + (lane >> 2) + h * 8;
            float* orow = obase + (size_t)row * OUT_F;
            #pragma unroll
            for (int f = 0; f < 8; ++f) {
                float v0 = acc[mf][f][2 * h]     + bs0[f];
                float v1 = acc[mf][f][2 * h + 1] + bs1[f];
                float o0 = even ? tanh_ap(v0) : fmaxf(v0, 0.0f);            // col%4 0|2
                float o1 = even ? sin_ap(v1)
                                : fmaf(0.5f, tanh_ap(0.5f * v1), 0.5f);     // col%4 1|3
                float2 o = { o0, o1 };
                *(float2*)(orow + f * 8) = o;
            }
        }
    }
}

// ---------------- launch ----------------
extern "C" void kernel_launch(void* const* d_in, const int* in_sizes, int n_in,
                              void* d_out, int out_size) {
    const float* X  = (const float*)d_in[0];
    const float* Wt = (const float*)d_in[1];
    const float* Bv = (const float*)d_in[2];
    float* O = (float*)d_out;

    const size_t total_vecs = XVECS + (size_t)OUT_F * IN_F / 8;
    cvt_xw_kernel<<<(int)(total_vecs / 256), 256>>>((const float4*)X, (const float4*)Wt);

    cudaFuncSetAttribute(gemm_act_kernel,
                         cudaFuncAttributeMaxDynamicSharedMemorySize, SMEM_TOTAL);
    gemm_act_kernel<<<(BATCH / BM) * (OUT_F / BN), NTHREADS, SMEM_TOTAL>>>(Bv, O);
}